// round 16
// baseline (speedup 1.0000x reference)
#include <cuda_runtime.h>
#include <cuda_bf16.h>
#include <cuda_fp16.h>

#define T_STEPS 100
#define BATCH   2048
#define NH      128
#define NORD    6
#define NSP     512

typedef unsigned long long ull;
typedef unsigned int u32;

// Scratch (device globals — no allocations allowed).
__device__ __align__(16) __half g_Wph[NSP * NH];   // Wc fp16 [outcol][k]
__device__ __align__(16) float g_bc[NSP];

__device__ __forceinline__ void ffma2(ull &d, ull a, ull b) {
    asm("fma.rn.f32x2 %0, %1, %2, %0;" : "+l"(d) : "l"(a), "l"(b));
}
__device__ __forceinline__ float sum2(ull a) {
    float lo, hi;
    asm("mov.b64 {%0,%1}, %2;" : "=f"(lo), "=f"(hi) : "l"(a));
    return lo + hi;
}
__device__ __forceinline__ u32 smem_u32(const void* p) {
    u32 a;
    asm("{ .reg .u64 t; cvta.to.shared.u64 t, %1; cvt.u32.u64 %0, t; }" : "=r"(a) : "l"(p));
    return a;
}
__device__ __forceinline__ __nv_bfloat162 split_bf(float x) {
    __nv_bfloat16 hi = __float2bfloat16(x);
    __nv_bfloat16 lo = __float2bfloat16(x - __bfloat162float(hi));
    __nv_bfloat162 r; r.x = hi; r.y = lo; return r;
}
__device__ __forceinline__ u32 us(__nv_bfloat16 b) {
    return (u32)__bfloat16_as_ushort(b);
}
__device__ __forceinline__ u32 uh(__half h) {
    return (u32)__half_as_ushort(h);
}
__device__ __forceinline__ void ldsm4(u32* r, u32 addr) {
    asm volatile("ldmatrix.sync.aligned.m8n8.x4.shared.b16 {%0,%1,%2,%3}, [%4];"
        : "=r"(r[0]), "=r"(r[1]), "=r"(r[2]), "=r"(r[3]) : "r"(addr));
}
__device__ __forceinline__ void mma16816(float* c, const u32* a, const u32* b) {
    asm volatile(
        "mma.sync.aligned.m16n8k16.row.col.f32.bf16.bf16.f32 "
        "{%0,%1,%2,%3}, {%4,%5,%6,%7}, {%8,%9}, {%0,%1,%2,%3};"
        : "+f"(c[0]), "+f"(c[1]), "+f"(c[2]), "+f"(c[3])
        : "r"(a[0]), "r"(a[1]), "r"(a[2]), "r"(a[3]), "r"(b[0]), "r"(b[1]));
}
__device__ __forceinline__ void mma16816h(float* c, const u32* a, const u32* b) {
    asm volatile(
        "mma.sync.aligned.m16n8k16.row.col.f32.f16.f16.f32 "
        "{%0,%1,%2,%3}, {%4,%5,%6,%7}, {%8,%9}, {%0,%1,%2,%3};"
        : "+f"(c[0]), "+f"(c[1]), "+f"(c[2]), "+f"(c[3])
        : "r"(a[0]), "r"(a[1]), "r"(a[2]), "r"(a[3]), "r"(b[0]), "r"(b[1]));
}
__device__ __forceinline__ void cp16(u32 s, const void* g) {
    asm volatile("cp.async.cg.shared.global [%0], [%1], 16;" :: "r"(s), "l"(g));
}

// W3 element (fused step weight), computed on the fly.
__device__ __forceinline__ float w3val(
    int j, int k, float mkbt,
    const float* __restrict__ he, const float* __restrict__ me,
    const float* __restrict__ ie, const float* __restrict__ ik,
    const float* __restrict__ hk, const float* __restrict__ mk,
    const float* __restrict__ AT, const float* __restrict__ BT) {
    if (j < 128) {
        if (k < 128) return hk[j * 128 + k] + mkbt * he[k];
        if (k < 134) {
            const int p = k - 128;
            float v = mkbt * me[p];
            #pragma unroll
            for (int o = 0; o < 6; o++)
                v += mk[j * 6 + o] * ((o == p ? 1.f : 0.f) + AT[o * 6 + p]);
            return v;
        }
        if (k < 136) return ik[j * 2 + (k - 134)] + mkbt * ie[k - 134];
        return 0.f;
    }
    if (j < 134) {
        const int o = j - 128;
        const float bt = BT[o];
        if (k < 128) return bt * he[k];
        if (k < 134) {
            const int p = k - 128;
            return (o == p ? 1.f : 0.f) + AT[o * 6 + p] + bt * me[p];
        }
        if (k < 136) return bt * ie[k - 134];
    }
    return 0.f;
}

// ---------------------------------------------------------------------------
// Kernel 1: combine. grid 128 x 256 thr. CTA owns 4 rows of Wc (fp16) + bias.
// ---------------------------------------------------------------------------
__global__ void __launch_bounds__(256) k_combine(
    const float* __restrict__ W_lin, const float* __restrict__ b_lin,
    const float* __restrict__ W_ssp, const float* __restrict__ b_ssp) {
    __shared__ float s[4 * 512];
    const int tid = threadIdx.x;
    const int i0 = blockIdx.x * 4;
    for (int i = tid; i < 512; i += 256)
        ((float4*)s)[i] = ((const float4*)(W_ssp + (size_t)i0 * 512))[i];
    __syncthreads();

    const int col = tid & 127;
    const int r0 = (tid >> 7) * 2;     // rows r0, r0+1
    float a0[4] = {0.f, 0.f, 0.f, 0.f};
    float a1[4] = {0.f, 0.f, 0.f, 0.f};
    #pragma unroll 4
    for (int j = 0; j < 512; j += 4) {
        #pragma unroll
        for (int u = 0; u < 4; u++) {
            const float wl = W_lin[(j + u) * 128 + col];
            a0[u] += s[r0 * 512 + j + u] * wl;
            a1[u] += s[(r0 + 1) * 512 + j + u] * wl;
        }
    }
    g_Wph[(size_t)(i0 + r0) * NH + col] =
        __float2half_rn((a0[0] + a0[1]) + (a0[2] + a0[3]));
    g_Wph[(size_t)(i0 + r0 + 1) * NH + col] =
        __float2half_rn((a1[0] + a1[1]) + (a1[2] + a1[3]));

    if (tid < 4) {
        float b0 = 0.f, b1 = 0.f, b2 = 0.f, b3 = 0.f;
        for (int j = 0; j < 512; j += 4) {
            const float4 b4 = *(const float4*)(b_lin + j);
            const float4 x4 = *(const float4*)(s + tid * 512 + j);
            b0 += x4.x * b4.x; b1 += x4.y * b4.y;
            b2 += x4.z * b4.z; b3 += x4.w * b4.w;
        }
        g_bc[i0 + tid] = b_ssp[i0 + tid] + (b0 + b1) + (b2 + b3);
    }
}

// ---------------------------------------------------------------------------
// Kernel 2: fused recurrence + per-step projection. grid 128 x 544 threads.
// Per CTA: 16 batch rows. Self-computes h0/m0 (staged GEMM, scratch aliases
// the Wc smem region) and W3 B-fragments; then per step: recurrence MMA ->
// h(t) -> [16x128]@Wc^T (fp16 HMMA, warps 0-15, 32 cols each) + bias -> out.
// Dynamic smem: Wc 131072 B | h-tile 4096 B  (scratch 39168 B aliases Wc).
// Static 32256 B + dynamic 135168 B -> opt-in attribute required.
// ---------------------------------------------------------------------------
__global__ void __launch_bounds__(544) k_recur(
    float* __restrict__ out,
    const float* __restrict__ vel,   const float* __restrict__ ssp,
    const float* __restrict__ w_c,   const float* __restrict__ w_h,
    const float* __restrict__ he,    const float* __restrict__ me,
    const float* __restrict__ ie,    const float* __restrict__ ik,
    const float* __restrict__ hk,    const float* __restrict__ mk,
    const float* __restrict__ AT,    const float* __restrict__ BT) {
    extern __shared__ float dsm[];
    __shared__ __align__(16) unsigned char s_xb[19456]; // 2 bufs x 2 planes x 16 x 304B
    __shared__ float s_v[3200];                         // [100][16][2]
    const int tid = threadIdx.x;
    const int b0 = blockIdx.x * 16;
    const u32 xb = smem_u32(s_xb);
    const u32 wcb = smem_u32(dsm);                      // Wc base, SHARED addr (asm only)
    const u32 hfb = wcb + 131072;                       // h-tile base, SHARED addr (asm only)
    unsigned char* hfp = (unsigned char*)dsm + 131072;  // h-tile base, GENERIC ptr (stores)
    const int lane = tid & 31, w = tid >> 5;

    for (int i = tid; i < 19456 / 4; i += 544) ((u32*)s_xb)[i] = 0;
    for (int i = tid; i < 3200; i += 544)
        s_v[i] = vel[(size_t)(i >> 5) * (BATCH * 2) + b0 * 2 + (i & 31)];

    // ---- W3 B-fragments from raw inputs ----
    const int colB = 8 * w + (lane >> 2);
    float mkbt = 0.f;
    if (colB < 128) {
        #pragma unroll
        for (int o = 0; o < 6; o++) mkbt += mk[colB * 6 + o] * BT[o];
    }
    u32 bh[9][2], bl[9][2];
    #pragma unroll
    for (int ks = 0; ks < 9; ks++) {
        #pragma unroll
        for (int rr = 0; rr < 2; rr++) {
            const int k0 = ks * 16 + 2 * (lane & 3) + rr * 8;
            const float v0 = w3val(colB, k0,     mkbt, he, me, ie, ik, hk, mk, AT, BT);
            const float v1 = w3val(colB, k0 + 1, mkbt, he, me, ie, ik, hk, mk, AT, BT);
            const __nv_bfloat162 p0 = split_bf(v0), p1 = split_bf(v1);
            bh[ks][rr] = us(p0.x) | (us(p1.x) << 16);
            bl[ks][rr] = us(p0.y) | (us(p1.y) << 16);
        }
    }

    // ---- setup GEMM: x0 = [h0 | m0] = ssp(16x512) @ [w_h; w_c]^T ----
    // scratch aliases the Wc region: s_w 136x64 @0, s_s 16x68 @8704 floats
    const int r_set = tid & 15;
    const int j_set = tid >> 4;          // 0..33; outputs j_set + 34u
    ull sac[4];
    #pragma unroll
    for (int u = 0; u < 4; u++) sac[u] = 0ull;

    #pragma unroll 1
    for (int kt = 0; kt < 8; kt++) {
        __syncthreads();     // scratch reuse (first iter also covers zero/s_v)
        for (int i = tid; i < 2176; i += 544) {
            const int row = i >> 4, c4 = i & 15;
            float4 v;
            if (row < 128)       v = *(const float4*)(w_h + row * 512 + kt * 64 + c4 * 4);
            else if (row < 134)  v = *(const float4*)(w_c + (row - 128) * 512 + kt * 64 + c4 * 4);
            else                 v = make_float4(0.f, 0.f, 0.f, 0.f);
            *(float4*)(dsm + row * 64 + c4 * 4) = v;
        }
        for (int i = tid; i < 256; i += 544) {
            const int row = i >> 4, c4 = i & 15;
            *(float4*)(dsm + 8704 + row * 68 + c4 * 4) =
                *(const float4*)(ssp + (size_t)(b0 + row) * 512 + kt * 64 + c4 * 4);
        }
        __syncthreads();
        #pragma unroll 4
        for (int k4 = 0; k4 < 16; k4++) {
            const ulonglong2 xp = *(const ulonglong2*)(dsm + 8704 + r_set * 68 + k4 * 4);
            #pragma unroll
            for (int u = 0; u < 4; u++) {
                const ulonglong2 wp = *(const ulonglong2*)(dsm + (j_set + 34 * u) * 64 + k4 * 4);
                ffma2(sac[u], xp.x, wp.x);
                ffma2(sac[u], xp.y, wp.y);
            }
        }
    }
    __syncthreads();   // all scratch reads done before Wc overwrites region

    // ---- stage Wc (128KB fp16, swizzled) via cp.async ----
    for (int idx = tid; idx < 8192; idx += 544) {
        const int row = idx >> 4, c16 = idx & 15;
        const u32 so = (u32)row * 256 + ((u32)((c16 ^ (row & 7)) << 4));
        cp16(wcb + so, g_Wph + (size_t)row * NH + c16 * 8);
    }
    asm volatile("cp.async.commit_group;");

    // write x(0) planes (hi at 0, lo at 4864)
    #pragma unroll
    for (int u = 0; u < 4; u++) {
        const int j = j_set + 34 * u;
        if (j < 134) {
            const __nv_bfloat162 p = split_bf(sum2(sac[u]));
            *(__nv_bfloat16*)(s_xb + r_set * 304 + j * 2) = p.x;
            *(__nv_bfloat16*)(s_xb + 4864 + r_set * 304 + j * 2) = p.y;
        }
    }
    if (tid < 32) {
        const int r = tid >> 1, c = tid & 1;
        const __nv_bfloat162 p = split_bf(s_v[r * 2 + c]);
        *(__nv_bfloat16*)(s_xb + r * 304 + (134 + c) * 2) = p.x;
        *(__nv_bfloat16*)(s_xb + 4864 + r * 304 + (134 + c) * 2) = p.y;
    }

    // ---- per-thread proj constants (warps 0-15 project 32 cols each) ----
    const int r0 = lane >> 2;
    const int c0 = 8 * w + 2 * (lane & 3);
    const u32 a_off = (u32)((lane & 15) * 304 + (lane >> 4) * 16);
    const int arow_l = lane & 15, asel = lane >> 4;
    const int brow_l = ((lane >> 4) << 3) + (lane & 7), bsel = (lane >> 3) & 1;
    const int tq = lane >> 2, tr = lane & 3;
    const int nbase = 32 * w;              // proj col block (w<16)
    float2 bias[4];
    if (w < 16) {
        #pragma unroll
        for (int nt = 0; nt < 4; nt++)
            bias[nt] = *(const float2*)(g_bc + nbase + nt * 8 + tr * 2);
    }
    asm volatile("cp.async.wait_group 0;");
    __syncthreads();

    // ---- main loop ----
    #pragma unroll 1
    for (int t = 0; t < T_STEPS; t++) {
        const u32 xro = (u32)(t & 1) * 9728;
        const u32 xwo = xro ^ 9728;
        float a_hh[4] = {0.f, 0.f, 0.f, 0.f};
        float a_lh[4] = {0.f, 0.f, 0.f, 0.f};
        float a_hl[4] = {0.f, 0.f, 0.f, 0.f};

        #pragma unroll
        for (int ks = 0; ks < 9; ks++) {
            u32 ah[4], al[4];
            ldsm4(ah, xb + xro + a_off + ks * 32);
            ldsm4(al, xb + xro + 4864 + a_off + ks * 32);
            mma16816(a_hh, ah, bh[ks]);
            mma16816(a_lh, al, bh[ks]);
            mma16816(a_hl, ah, bl[ks]);
        }
        float acc[4];
        #pragma unroll
        for (int i = 0; i < 4; i++) acc[i] = a_hh[i] + (a_lh[i] + a_hl[i]);

        if (c0 < 128) {
            float hv[4];
            #pragma unroll
            for (int i = 0; i < 4; i++) {
                const float e = __expf(2.f * acc[i]);
                hv[i] = 1.f - __fdividef(2.f, e + 1.f);
            }
            const __nv_bfloat162 s00 = split_bf(hv[0]), s01 = split_bf(hv[1]);
            const __nv_bfloat162 s10 = split_bf(hv[2]), s11 = split_bf(hv[3]);
            *(u32*)(s_xb + xwo + r0 * 304 + c0 * 2)              = us(s00.x) | (us(s01.x) << 16);
            *(u32*)(s_xb + xwo + 4864 + r0 * 304 + c0 * 2)       = us(s00.y) | (us(s01.y) << 16);
            *(u32*)(s_xb + xwo + (r0 + 8) * 304 + c0 * 2)        = us(s10.x) | (us(s11.x) << 16);
            *(u32*)(s_xb + xwo + 4864 + (r0 + 8) * 304 + c0 * 2) = us(s10.y) | (us(s11.y) << 16);
            // fp16 h tile for this step's projection (swizzled; GENERIC ptr)
            const u32 bo = ((u32)(w ^ r0) << 4) + (u32)(lane & 3) * 4;
            *(u32*)(hfp + (u32)r0 * 256 + bo) =
                uh(__float2half_rn(hv[0])) | (uh(__float2half_rn(hv[1])) << 16);
            *(u32*)(hfp + (u32)(r0 + 8) * 256 + bo) =
                uh(__float2half_rn(hv[2])) | (uh(__float2half_rn(hv[3])) << 16);
        } else if (c0 < 134) {
            const __nv_bfloat162 s00 = split_bf(acc[0]), s01 = split_bf(acc[1]);
            const __nv_bfloat162 s10 = split_bf(acc[2]), s11 = split_bf(acc[3]);
            *(u32*)(s_xb + xwo + r0 * 304 + c0 * 2)        = us(s00.x) | (us(s01.x) << 16);
            *(u32*)(s_xb + xwo + 4864 + r0 * 304 + c0 * 2) = us(s00.y) | (us(s01.y) << 16);
            *(u32*)(s_xb + xwo + (r0 + 8) * 304 + c0 * 2)        = us(s10.x) | (us(s11.x) << 16);
            *(u32*)(s_xb + xwo + 4864 + (r0 + 8) * 304 + c0 * 2) = us(s10.y) | (us(s11.y) << 16);
        } else if (t < T_STEPS - 1) {
            const __nv_bfloat162 a0 = split_bf(s_v[(t + 1) * 32 + r0 * 2]);
            const __nv_bfloat162 a1 = split_bf(s_v[(t + 1) * 32 + r0 * 2 + 1]);
            const __nv_bfloat162 b0s = split_bf(s_v[(t + 1) * 32 + (r0 + 8) * 2]);
            const __nv_bfloat162 b1s = split_bf(s_v[(t + 1) * 32 + (r0 + 8) * 2 + 1]);
            *(u32*)(s_xb + xwo + r0 * 304 + 268)        = us(a0.x) | (us(a1.x) << 16);
            *(u32*)(s_xb + xwo + 4864 + r0 * 304 + 268) = us(a0.y) | (us(a1.y) << 16);
            *(u32*)(s_xb + xwo + (r0 + 8) * 304 + 268)        = us(b0s.x) | (us(b1s.x) << 16);
            *(u32*)(s_xb + xwo + 4864 + (r0 + 8) * 304 + 268) = us(b0s.y) | (us(b1s.y) << 16);
        }
        __syncthreads();    // h-tile + x(t+1) visible

        // ---- fused projection: out(t) = h(t) @ Wc^T + bc ----
        if (w < 16) {
            float pacc[4][4];
            #pragma unroll
            for (int nt = 0; nt < 4; nt++)
                #pragma unroll
                for (int i = 0; i < 4; i++) pacc[nt][i] = 0.f;

            #pragma unroll
            for (int ks = 0; ks < 8; ks++) {
                u32 af[4];
                const u32 aoff = (u32)arow_l * 256 +
                                 ((u32)(((2 * ks + asel) ^ (arow_l & 7)) << 4));
                ldsm4(af, hfb + aoff);
                u32 bf[2][4];
                #pragma unroll
                for (int np = 0; np < 2; np++) {
                    const int brow = nbase + np * 16 + brow_l;
                    const u32 boff = (u32)brow * 256 +
                                     ((u32)(((2 * ks + bsel) ^ (brow & 7)) << 4));
                    ldsm4(bf[np], wcb + boff);
                }
                #pragma unroll
                for (int nt = 0; nt < 4; nt++)
                    mma16816h(pacc[nt], af, &bf[nt >> 1][(nt & 1) * 2]);
            }

            float* op = out + ((size_t)t * BATCH + b0) * NSP;
            #pragma unroll
            for (int nt = 0; nt < 4; nt++) {
                const int ncol = nbase + nt * 8 + tr * 2;
                float2 v0, v1;
                v0.x = pacc[nt][0] + bias[nt].x; v0.y = pacc[nt][1] + bias[nt].y;
                v1.x = pacc[nt][2] + bias[nt].x; v1.y = pacc[nt][3] + bias[nt].y;
                *(float2*)(op + (size_t)tq * NSP + ncol) = v0;
                *(float2*)(op + (size_t)(tq + 8) * NSP + ncol) = v1;
            }
        }
        __syncthreads();    // proj reads done before next step overwrites
    }
}

// ---------------------------------------------------------------------------
extern "C" void kernel_launch(void* const* d_in, const int* in_sizes, int n_in,
                              void* d_out, int out_size) {
    const float* vel   = (const float*)d_in[0];
    const float* ssp0  = (const float*)d_in[1];
    const float* ie    = (const float*)d_in[2];
    const float* he    = (const float*)d_in[3];
    const float* me    = (const float*)d_in[4];
    const float* ik    = (const float*)d_in[5];
    const float* hk    = (const float*)d_in[6];
    const float* mk    = (const float*)d_in[7];
    const float* AT    = (const float*)d_in[8];
    const float* BT    = (const float*)d_in[9];
    const float* w_c   = (const float*)d_in[10];
    const float* w_h   = (const float*)d_in[11];
    const float* W_lin = (const float*)d_in[12];
    const float* b_lin = (const float*)d_in[13];
    const float* W_ssp = (const float*)d_in[14];
    const float* b_ssp = (const float*)d_in[15];
    float* out = (float*)d_out;

    const int recur_dsm = 131072 + 4096;   // Wc + h-tile (scratch aliases Wc)
    cudaFuncSetAttribute(k_recur, cudaFuncAttributeMaxDynamicSharedMemorySize, recur_dsm);

    k_combine<<<128, 256>>>(W_lin, b_lin, W_ssp, b_ssp);
    k_recur<<<128, 544, recur_dsm>>>(out, vel, ssp0, w_c, w_h,
                                     he, me, ie, ik, hk, mk, AT, BT);
}

// round 17
// speedup vs baseline: 1.3272x; 1.3272x over previous
#include <cuda_runtime.h>
#include <cuda_bf16.h>
#include <cuda_fp16.h>

#define T_STEPS 100
#define BATCH   2048
#define NH      128
#define NORD    6
#define NSP     512

typedef unsigned long long ull;
typedef unsigned int u32;

// Scratch (device globals — no allocations allowed).
__device__ __align__(16) __half g_Hf[(size_t)T_STEPS * BATCH * NH];  // fp16 h plane
__device__ __align__(16) __half g_Wph[NSP * NH];                     // Wc fp16 plane
__device__ __align__(16) float g_bc[NSP];

__device__ __forceinline__ void ffma2(ull &d, ull a, ull b) {
    asm("fma.rn.f32x2 %0, %1, %2, %0;" : "+l"(d) : "l"(a), "l"(b));
}
__device__ __forceinline__ float sum2(ull a) {
    float lo, hi;
    asm("mov.b64 {%0,%1}, %2;" : "=f"(lo), "=f"(hi) : "l"(a));
    return lo + hi;
}
__device__ __forceinline__ u32 smem_u32(const void* p) {
    u32 a;
    asm("{ .reg .u64 t; cvta.to.shared.u64 t, %1; cvt.u32.u64 %0, t; }" : "=r"(a) : "l"(p));
    return a;
}
__device__ __forceinline__ __nv_bfloat162 split_bf(float x) {
    __nv_bfloat16 hi = __float2bfloat16(x);
    __nv_bfloat16 lo = __float2bfloat16(x - __bfloat162float(hi));
    __nv_bfloat162 r; r.x = hi; r.y = lo; return r;
}
__device__ __forceinline__ u32 us(__nv_bfloat16 b) {
    return (u32)__bfloat16_as_ushort(b);
}
__device__ __forceinline__ u32 uh(__half h) {
    return (u32)__half_as_ushort(h);
}
__device__ __forceinline__ void ldsm4(u32* r, u32 addr) {
    asm volatile("ldmatrix.sync.aligned.m8n8.x4.shared.b16 {%0,%1,%2,%3}, [%4];"
        : "=r"(r[0]), "=r"(r[1]), "=r"(r[2]), "=r"(r[3]) : "r"(addr));
}
__device__ __forceinline__ void mma16816(float* c, const u32* a, const u32* b) {
    asm volatile(
        "mma.sync.aligned.m16n8k16.row.col.f32.bf16.bf16.f32 "
        "{%0,%1,%2,%3}, {%4,%5,%6,%7}, {%8,%9}, {%0,%1,%2,%3};"
        : "+f"(c[0]), "+f"(c[1]), "+f"(c[2]), "+f"(c[3])
        : "r"(a[0]), "r"(a[1]), "r"(a[2]), "r"(a[3]), "r"(b[0]), "r"(b[1]));
}
__device__ __forceinline__ void mma16816h(float* c, const u32* a, const u32* b) {
    asm volatile(
        "mma.sync.aligned.m16n8k16.row.col.f32.f16.f16.f32 "
        "{%0,%1,%2,%3}, {%4,%5,%6,%7}, {%8,%9}, {%0,%1,%2,%3};"
        : "+f"(c[0]), "+f"(c[1]), "+f"(c[2]), "+f"(c[3])
        : "r"(a[0]), "r"(a[1]), "r"(a[2]), "r"(a[3]), "r"(b[0]), "r"(b[1]));
}
__device__ __forceinline__ void cp16(u32 s, const void* g) {
    asm volatile("cp.async.cg.shared.global [%0], [%1], 16;" :: "r"(s), "l"(g));
}

// W3 element (fused step weight), computed on the fly.
__device__ __forceinline__ float w3val(
    int j, int k, float mkbt,
    const float* __restrict__ he, const float* __restrict__ me,
    const float* __restrict__ ie, const float* __restrict__ ik,
    const float* __restrict__ hk, const float* __restrict__ mk,
    const float* __restrict__ AT, const float* __restrict__ BT) {
    if (j < 128) {
        if (k < 128) return hk[j * 128 + k] + mkbt * he[k];
        if (k < 134) {
            const int p = k - 128;
            float v = mkbt * me[p];
            #pragma unroll
            for (int o = 0; o < 6; o++)
                v += mk[j * 6 + o] * ((o == p ? 1.f : 0.f) + AT[o * 6 + p]);
            return v;
        }
        if (k < 136) return ik[j * 2 + (k - 134)] + mkbt * ie[k - 134];
        return 0.f;
    }
    if (j < 134) {
        const int o = j - 128;
        const float bt = BT[o];
        if (k < 128) return bt * he[k];
        if (k < 134) {
            const int p = k - 128;
            return (o == p ? 1.f : 0.f) + AT[o * 6 + p] + bt * me[p];
        }
        if (k < 136) return bt * ie[k - 134];
    }
    return 0.f;
}

// ---------------------------------------------------------------------------
// Kernel 1: recurrence + embedded init (EXACTLY as R14). grid 160 x 544.
//   bids [0,128):   recur CTA (16 batch rows)
//   bids [128,160): combine CTA: 16 rows of Wc (fp16) + bc
// ---------------------------------------------------------------------------
__global__ void __launch_bounds__(544) k_recur(
    const float* __restrict__ vel,   const float* __restrict__ ssp,
    const float* __restrict__ w_c,   const float* __restrict__ w_h,
    const float* __restrict__ W_lin, const float* __restrict__ b_lin,
    const float* __restrict__ W_ssp, const float* __restrict__ b_ssp,
    const float* __restrict__ he,    const float* __restrict__ me,
    const float* __restrict__ ie,    const float* __restrict__ ik,
    const float* __restrict__ hk,    const float* __restrict__ mk,
    const float* __restrict__ AT,    const float* __restrict__ BT) {
    extern __shared__ float dsm[];
    const int tid = threadIdx.x;
    const int bid = blockIdx.x;

    if (bid >= 128) {
        // ================= combine CTA =================
        const int i0 = (bid - 128) * 16;
        for (int i = tid; i < 2048; i += 544)
            ((float4*)dsm)[i] = ((const float4*)(W_ssp + (size_t)i0 * 512))[i];
        __syncthreads();
        if (tid < 512) {
            const int col = tid & 127;
            const int rb = tid >> 7;
            float a[4][4];
            #pragma unroll
            for (int rr = 0; rr < 4; rr++)
                #pragma unroll
                for (int u = 0; u < 4; u++) a[rr][u] = 0.f;
            for (int j = 0; j < 512; j += 4) {
                float wl[4];
                #pragma unroll
                for (int u = 0; u < 4; u++) wl[u] = W_lin[(j + u) * 128 + col];
                #pragma unroll
                for (int rr = 0; rr < 4; rr++) {
                    const float4 x4 = *(const float4*)(dsm + (rb + 4 * rr) * 512 + j);
                    a[rr][0] += x4.x * wl[0]; a[rr][1] += x4.y * wl[1];
                    a[rr][2] += x4.z * wl[2]; a[rr][3] += x4.w * wl[3];
                }
            }
            #pragma unroll
            for (int rr = 0; rr < 4; rr++) {
                const float v = (a[rr][0] + a[rr][1]) + (a[rr][2] + a[rr][3]);
                g_Wph[(size_t)(i0 + rb + 4 * rr) * NH + col] = __float2half_rn(v);
            }
        } else if (tid < 528) {
            const int row = tid - 512;
            float a0 = 0.f, a1 = 0.f, a2 = 0.f, a3 = 0.f;
            for (int j = 0; j < 512; j += 4) {
                const float4 b4 = *(const float4*)(b_lin + j);
                const float4 x4 = *(const float4*)(dsm + row * 512 + j);
                a0 += x4.x * b4.x; a1 += x4.y * b4.y;
                a2 += x4.z * b4.z; a3 += x4.w * b4.w;
            }
            g_bc[i0 + row] = b_ssp[i0 + row] + (a0 + a1) + (a2 + a3);
        }
        return;
    }

    // ================= recur CTA =================
    __shared__ __align__(16) unsigned char s_xb[19456];
    __shared__ float s_v[3200];
    const int b0 = bid * 16;
    const u32 xb = smem_u32(s_xb);
    const int lane = tid & 31, w = tid >> 5;

    for (int i = tid; i < 19456 / 4; i += 544) ((u32*)s_xb)[i] = 0;
    for (int i = tid; i < 3200; i += 544)
        s_v[i] = vel[(size_t)(i >> 5) * (BATCH * 2) + b0 * 2 + (i & 31)];

    const int colB = 8 * w + (lane >> 2);
    float mkbt = 0.f;
    if (colB < 128) {
        #pragma unroll
        for (int o = 0; o < 6; o++) mkbt += mk[colB * 6 + o] * BT[o];
    }
    u32 bh[9][2], bl[9][2];
    #pragma unroll
    for (int ks = 0; ks < 9; ks++) {
        #pragma unroll
        for (int rr = 0; rr < 2; rr++) {
            const int k0 = ks * 16 + 2 * (lane & 3) + rr * 8;
            const float v0 = w3val(colB, k0,     mkbt, he, me, ie, ik, hk, mk, AT, BT);
            const float v1 = w3val(colB, k0 + 1, mkbt, he, me, ie, ik, hk, mk, AT, BT);
            const __nv_bfloat162 p0 = split_bf(v0), p1 = split_bf(v1);
            bh[ks][rr] = us(p0.x) | (us(p1.x) << 16);
            bl[ks][rr] = us(p0.y) | (us(p1.y) << 16);
        }
    }

    const int r_set = tid & 15;
    const int j_set = tid >> 4;
    ull sac[4];
    #pragma unroll
    for (int u = 0; u < 4; u++) sac[u] = 0ull;

    #pragma unroll 1
    for (int kt = 0; kt < 8; kt++) {
        __syncthreads();
        for (int i = tid; i < 2176; i += 544) {
            const int row = i >> 4, c4 = i & 15;
            float4 v;
            if (row < 128)       v = *(const float4*)(w_h + row * 512 + kt * 64 + c4 * 4);
            else if (row < 134)  v = *(const float4*)(w_c + (row - 128) * 512 + kt * 64 + c4 * 4);
            else                 v = make_float4(0.f, 0.f, 0.f, 0.f);
            *(float4*)(dsm + row * 64 + c4 * 4) = v;
        }
        for (int i = tid; i < 256; i += 544) {
            const int row = i >> 4, c4 = i & 15;
            *(float4*)(dsm + 8704 + row * 68 + c4 * 4) =
                *(const float4*)(ssp + (size_t)(b0 + row) * 512 + kt * 64 + c4 * 4);
        }
        __syncthreads();
        #pragma unroll 4
        for (int k4 = 0; k4 < 16; k4++) {
            const ulonglong2 xp = *(const ulonglong2*)(dsm + 8704 + r_set * 68 + k4 * 4);
            #pragma unroll
            for (int u = 0; u < 4; u++) {
                const ulonglong2 wp = *(const ulonglong2*)(dsm + (j_set + 34 * u) * 64 + k4 * 4);
                ffma2(sac[u], xp.x, wp.x);
                ffma2(sac[u], xp.y, wp.y);
            }
        }
    }
    #pragma unroll
    for (int u = 0; u < 4; u++) {
        const int j = j_set + 34 * u;
        if (j < 134) {
            const __nv_bfloat162 p = split_bf(sum2(sac[u]));
            *(__nv_bfloat16*)(s_xb + r_set * 304 + j * 2) = p.x;
            *(__nv_bfloat16*)(s_xb + 4864 + r_set * 304 + j * 2) = p.y;
        }
    }
    if (tid < 32) {
        const int r = tid >> 1, c = tid & 1;
        const __nv_bfloat162 p = split_bf(s_v[r * 2 + c]);
        *(__nv_bfloat16*)(s_xb + r * 304 + (134 + c) * 2) = p.x;
        *(__nv_bfloat16*)(s_xb + 4864 + r * 304 + (134 + c) * 2) = p.y;
    }
    __syncthreads();

    const int r0 = lane >> 2;
    const int c0 = 8 * w + 2 * (lane & 3);
    const u32 a_off = (u32)((lane & 15) * 304 + (lane >> 4) * 16);

    #pragma unroll 1
    for (int t = 0; t < T_STEPS; t++) {
        const u32 xro = (u32)(t & 1) * 9728;
        const u32 xwo = xro ^ 9728;
        float a_hh[4] = {0.f, 0.f, 0.f, 0.f};
        float a_lh[4] = {0.f, 0.f, 0.f, 0.f};
        float a_hl[4] = {0.f, 0.f, 0.f, 0.f};

        #pragma unroll
        for (int ks = 0; ks < 9; ks++) {
            u32 ah[4], al[4];
            ldsm4(ah, xb + xro + a_off + ks * 32);
            ldsm4(al, xb + xro + 4864 + a_off + ks * 32);
            mma16816(a_hh, ah, bh[ks]);
            mma16816(a_lh, al, bh[ks]);
            mma16816(a_hl, ah, bl[ks]);
        }
        float acc[4];
        #pragma unroll
        for (int i = 0; i < 4; i++) acc[i] = a_hh[i] + (a_lh[i] + a_hl[i]);

        if (c0 < 128) {
            float hv[4];
            #pragma unroll
            for (int i = 0; i < 4; i++) {
                const float e = __expf(2.f * acc[i]);
                hv[i] = 1.f - __fdividef(2.f, e + 1.f);
            }
            const __nv_bfloat162 s00 = split_bf(hv[0]), s01 = split_bf(hv[1]);
            const __nv_bfloat162 s10 = split_bf(hv[2]), s11 = split_bf(hv[3]);
            *(u32*)(s_xb + xwo + r0 * 304 + c0 * 2)              = us(s00.x) | (us(s01.x) << 16);
            *(u32*)(s_xb + xwo + 4864 + r0 * 304 + c0 * 2)       = us(s00.y) | (us(s01.y) << 16);
            *(u32*)(s_xb + xwo + (r0 + 8) * 304 + c0 * 2)        = us(s10.x) | (us(s11.x) << 16);
            *(u32*)(s_xb + xwo + 4864 + (r0 + 8) * 304 + c0 * 2) = us(s10.y) | (us(s11.y) << 16);
            const size_t go = ((size_t)t * BATCH + b0 + r0) * NH + c0;
            *(u32*)(g_Hf + go) =
                uh(__float2half_rn(hv[0])) | (uh(__float2half_rn(hv[1])) << 16);
            *(u32*)(g_Hf + go + 8 * NH) =
                uh(__float2half_rn(hv[2])) | (uh(__float2half_rn(hv[3])) << 16);
        } else if (c0 < 134) {
            const __nv_bfloat162 s00 = split_bf(acc[0]), s01 = split_bf(acc[1]);
            const __nv_bfloat162 s10 = split_bf(acc[2]), s11 = split_bf(acc[3]);
            *(u32*)(s_xb + xwo + r0 * 304 + c0 * 2)        = us(s00.x) | (us(s01.x) << 16);
            *(u32*)(s_xb + xwo + 4864 + r0 * 304 + c0 * 2) = us(s00.y) | (us(s01.y) << 16);
            *(u32*)(s_xb + xwo + (r0 + 8) * 304 + c0 * 2)        = us(s10.x) | (us(s11.x) << 16);
            *(u32*)(s_xb + xwo + 4864 + (r0 + 8) * 304 + c0 * 2) = us(s10.y) | (us(s11.y) << 16);
        } else if (t < T_STEPS - 1) {
            const __nv_bfloat162 a0 = split_bf(s_v[(t + 1) * 32 + r0 * 2]);
            const __nv_bfloat162 a1 = split_bf(s_v[(t + 1) * 32 + r0 * 2 + 1]);
            const __nv_bfloat162 b0s = split_bf(s_v[(t + 1) * 32 + (r0 + 8) * 2]);
            const __nv_bfloat162 b1s = split_bf(s_v[(t + 1) * 32 + (r0 + 8) * 2 + 1]);
            *(u32*)(s_xb + xwo + r0 * 304 + 268)        = us(a0.x) | (us(a1.x) << 16);
            *(u32*)(s_xb + xwo + 4864 + r0 * 304 + 268) = us(a0.y) | (us(a1.y) << 16);
            *(u32*)(s_xb + xwo + (r0 + 8) * 304 + 268)        = us(b0s.x) | (us(b1s.x) << 16);
            *(u32*)(s_xb + xwo + 4864 + (r0 + 8) * 304 + 268) = us(b0s.y) | (us(b1s.y) << 16);
        }
        __syncthreads();
    }
}

// ---------------------------------------------------------------------------
// Kernel 2: projection v6 — fp16 single-pass HMMA, K-half pipelined cp.async,
// streaming stores. CTA 128x128, buffers B0|B1|A0|A1 16KB each = 64KB.
// ---------------------------------------------------------------------------
#define PJ_B0 0
#define PJ_B1 16384
#define PJ_A0 32768
#define PJ_A1 49152
#define PJ_SMEM 65536

__global__ void __launch_bounds__(256, 2) k_proj(float* __restrict__ out) {
    extern __shared__ char smc[];
    const u32 sb = smem_u32(smc);
    const int tid = threadIdx.x;
    const int w = tid >> 5, lane = tid & 31;
    const int col0 = blockIdx.x * 128;
    const int row0 = blockIdx.y * 128;

    const int wm = w & 1, wn = w >> 1;
    const int mbase = wm * 64, nbase = wn * 32;
    const int arow_l = lane & 15, asel = lane >> 4;
    const int brow_l = ((lane >> 4) << 3) + (lane & 7), bsel = (lane >> 3) & 1;

    // Issue half 0 loads, commit; then half 1 loads, commit.
    #pragma unroll
    for (int half = 0; half < 2; half++) {
        const u32 ab = sb + PJ_A0 + half * 16384;
        const u32 bb = sb + PJ_B0 + half * 16384;
        for (int idx = tid; idx < 1024; idx += 256) {
            const int row = idx >> 3, c16 = idx & 7;
            const u32 so = (u32)row * 128 + ((u32)((c16 ^ (row & 7)) << 4));
            cp16(ab + so, g_Hf + (size_t)(row0 + row) * NH + half * 64 + c16 * 8);
            cp16(bb + so, g_Wph + (size_t)(col0 + row) * NH + half * 64 + c16 * 8);
        }
        asm volatile("cp.async.commit_group;");
    }

    float acc[4][4][4];
    #pragma unroll
    for (int mt = 0; mt < 4; mt++)
        #pragma unroll
        for (int nt = 0; nt < 4; nt++)
            #pragma unroll
            for (int i = 0; i < 4; i++) acc[mt][nt][i] = 0.f;

    // half 0 compute overlaps half 1 loads
    asm volatile("cp.async.wait_group 1;");
    __syncthreads();
    #pragma unroll
    for (int half = 0; half < 2; half++) {
        if (half) {
            asm volatile("cp.async.wait_group 0;");
            __syncthreads();
        }
        const u32 ab = sb + PJ_A0 + half * 16384;
        const u32 bb = sb + PJ_B0 + half * 16384;
        #pragma unroll
        for (int kk = 0; kk < 4; kk++) {
            u32 a[4][4];
            #pragma unroll
            for (int mt = 0; mt < 4; mt++) {
                const int row = mbase + mt * 16 + arow_l;
                const u32 off = (u32)row * 128 + ((u32)(((2 * kk + asel) ^ (row & 7)) << 4));
                ldsm4(a[mt], ab + off);
            }
            u32 bf[2][4];
            #pragma unroll
            for (int np = 0; np < 2; np++) {
                const int row = nbase + np * 16 + brow_l;
                const u32 off = (u32)row * 128 + ((u32)(((2 * kk + bsel) ^ (row & 7)) << 4));
                ldsm4(bf[np], bb + off);
            }
            #pragma unroll
            for (int mt = 0; mt < 4; mt++)
                #pragma unroll
                for (int nt = 0; nt < 4; nt++)
                    mma16816h(acc[mt][nt], a[mt], &bf[nt >> 1][(nt & 1) * 2]);
        }
    }

    const int tq = lane >> 2, tr = lane & 3;
    #pragma unroll
    for (int nt = 0; nt < 4; nt++) {
        const int ncol = col0 + nbase + nt * 8 + tr * 2;
        const float2 bias = *(const float2*)(g_bc + ncol);
        #pragma unroll
        for (int mt = 0; mt < 4; mt++) {
            const int mrow = row0 + mbase + mt * 16 + tq;
            float2 v0, v1;
            v0.x = acc[mt][nt][0] + bias.x; v0.y = acc[mt][nt][1] + bias.y;
            v1.x = acc[mt][nt][2] + bias.x; v1.y = acc[mt][nt][3] + bias.y;
            __stcs((float2*)(out + (size_t)mrow * NSP + ncol), v0);
            __stcs((float2*)(out + (size_t)(mrow + 8) * NSP + ncol), v1);
        }
    }
}

// ---------------------------------------------------------------------------
extern "C" void kernel_launch(void* const* d_in, const int* in_sizes, int n_in,
                              void* d_out, int out_size) {
    const float* vel   = (const float*)d_in[0];
    const float* ssp0  = (const float*)d_in[1];
    const float* ie    = (const float*)d_in[2];
    const float* he    = (const float*)d_in[3];
    const float* me    = (const float*)d_in[4];
    const float* ik    = (const float*)d_in[5];
    const float* hk    = (const float*)d_in[6];
    const float* mk    = (const float*)d_in[7];
    const float* AT    = (const float*)d_in[8];
    const float* BT    = (const float*)d_in[9];
    const float* w_c   = (const float*)d_in[10];
    const float* w_h   = (const float*)d_in[11];
    const float* W_lin = (const float*)d_in[12];
    const float* b_lin = (const float*)d_in[13];
    const float* W_ssp = (const float*)d_in[14];
    const float* b_ssp = (const float*)d_in[15];
    float* out = (float*)d_out;

    const int recur_dsm = (136 * 64 + 16 * 68) * 4;   // 39168 B
    cudaFuncSetAttribute(k_recur, cudaFuncAttributeMaxDynamicSharedMemorySize, recur_dsm);
    cudaFuncSetAttribute(k_proj,  cudaFuncAttributeMaxDynamicSharedMemorySize, PJ_SMEM);

    k_recur<<<160, 544, recur_dsm>>>(vel, ssp0, w_c, w_h, W_lin, b_lin, W_ssp, b_ssp,
                                     he, me, ie, ik, hk, mk, AT, BT);
    dim3 g(4, 1600);
    k_proj<<<g, 256, PJ_SMEM>>>(out);
}